// round 14
// baseline (speedup 1.0000x reference)
#include <cuda_runtime.h>
#include <cuda_bf16.h>
#include <cstdint>

#define KB   2
#define KH   16
#define KSQ  2048
#define KSK  2048
#define TQ   64
#define TK   64
#define NT   512            // 8 compute warps + 8 hash warps
#define NTILES (KSK / TK)

#define KEEP_THRESH 0xE6666600u      // jax uniform(bits) < 0.9f
#define L2E  1.4426950408889634f
#define NEGC (-30.0f * 1.4426950408889634f)   // fixed shift C=30 in log2 units

// ---- smem byte offsets (R6 double-buffered layout + mask ring) ----
#define SM_PHI   0
#define SM_PLO   8192
#define SM_KHI(s) (16384 + (s)*16384)
#define SM_KLO(s) (16384 + (s)*16384 + 8192)
#define SM_VHI(s) (49152 + (s)*16384)
#define SM_VLO(s) (49152 + (s)*16384 + 8192)
#define SM_LRED  81920        // 128 floats
#define SM_MRING 82432        // 2 slots x 256 uint32 = 2048 B
#define SMEM_BYTES 84480

__device__ __forceinline__ uint32_t smem_u32(const void* p) {
    uint32_t a;
    asm("{ .reg .u64 t; cvta.to.shared.u64 t, %1; cvt.u32.u64 %0, t; }"
        : "=r"(a) : "l"(p));
    return a;
}
__device__ __forceinline__ unsigned long long pku64(uint32_t lo, uint32_t hi) {
    unsigned long long r;
    asm("mov.b64 %0, {%1, %2};" : "=l"(r) : "r"(lo), "r"(hi));
    return r;
}
#define STS64(addr, v) \
    asm volatile("st.shared.b64 [%0], %1;" :: "r"(addr), "l"(v) : "memory")
#define STS32(addr, v) \
    asm volatile("st.shared.b32 [%0], %1;" :: "r"(addr), "r"(v) : "memory")
__device__ __forceinline__ float ex2f(float x) {
    float r; asm("ex2.approx.f32 %0, %1;" : "=f"(r) : "f"(x)); return r;
}
// split floats a,b -> bf16x2 hi (a low half) + bf16x2 lo residual
__device__ __forceinline__ void split2(float a, float b, uint32_t& hi, uint32_t& lo) {
    uint32_t h;
    asm("cvt.rn.bf16x2.f32 %0, %1, %2;" : "=r"(h) : "f"(b), "f"(a));
    float ha = __uint_as_float(h << 16);
    float hb = __uint_as_float(h & 0xFFFF0000u);
    float la = a - ha, lb = b - hb;
    uint32_t l;
    asm("cvt.rn.bf16x2.f32 %0, %1, %2;" : "=r"(l) : "f"(lb), "f"(la));
    hi = h; lo = l;
}

#define LDMX4(r, addr) \
    asm volatile("ldmatrix.sync.aligned.m8n8.x4.shared.b16 {%0,%1,%2,%3}, [%4];" \
        : "=r"((r)[0]), "=r"((r)[1]), "=r"((r)[2]), "=r"((r)[3]) : "r"(addr))

#define MMA16816(d, a, b0, b1) \
    asm volatile("mma.sync.aligned.m16n8k16.row.col.f32.bf16.bf16.f32 " \
        "{%0,%1,%2,%3}, {%4,%5,%6,%7}, {%8,%9}, {%0,%1,%2,%3};" \
        : "+f"((d)[0]), "+f"((d)[1]), "+f"((d)[2]), "+f"((d)[3]) \
        : "r"((a)[0]), "r"((a)[1]), "r"((a)[2]), "r"((a)[3]), "r"(b0), "r"(b1))

// JAX partitionable threefry, key=(0,42): bits = y0 ^ y1  (bit-exact, R6 form)
__device__ __forceinline__ uint32_t tf32_hash(uint32_t idx) {
    const uint32_t ks1 = 42u;
    const uint32_t ks2 = 42u ^ 0x1BD11BDAu;
    uint32_t x0 = 0u;
    uint32_t x1 = idx + ks1;
#define TFR(r) { x0 += x1; x1 = __funnelshift_l(x1, x1, (r)); x1 ^= x0; }
    TFR(13) TFR(15) TFR(26) TFR(6)
    x0 += ks1; x1 += ks2 + 1u;
    TFR(17) TFR(29) TFR(16) TFR(24)
    x0 += ks2; x1 += 2u;
    TFR(13) TFR(15) TFR(26) TFR(6)
    x1 += ks1 + 3u;
    TFR(17) TFR(29) TFR(16) TFR(24)
    x0 += ks1; x1 += ks2 + 4u;
    TFR(13) TFR(15) TFR(26) TFR(6)
    x0 += ks2; x1 += 5u;
#undef TFR
    return x0 ^ x1;
}

// 16 mask bits for one (virtual) compute lane, tile starting at k0.
// Bit layout identical to the R9/R10 producer (verified bit-exact).
__device__ __forceinline__ uint32_t make_mask(uint32_t hb0, uint32_t hb1,
                                              int k0, int wk, int cp) {
    const uint32_t kb0 = hb0 | (uint32_t)(k0 + wk * 32);
    const uint32_t kb1 = hb1 | (uint32_t)(k0 + wk * 32);
    uint32_t m = 0;
    #pragma unroll
    for (int nt = 0; nt < 4; ++nt) {
        uint32_t colw = (uint32_t)(nt * 8 + cp);
        m |= (tf32_hash(kb0 + colw)      < KEEP_THRESH ? 1u : 0u) << (nt * 4);
        m |= (tf32_hash(kb0 + colw + 1u) < KEEP_THRESH ? 1u : 0u) << (nt * 4 + 1);
        m |= (tf32_hash(kb1 + colw)      < KEEP_THRESH ? 1u : 0u) << (nt * 4 + 2);
        m |= (tf32_hash(kb1 + colw + 1u) < KEEP_THRESH ? 1u : 0u) << (nt * 4 + 3);
    }
    return m;
}

// K tile [64k][64d] and V^T tile [64dv][64k] -> split bf16, SW128 rows (128B).
// Executed by the 256 compute threads (tid 0..255).
__device__ __forceinline__ void load_kv(uint32_t sb, int st,
                                        const float4* __restrict__ kg4,
                                        const float* __restrict__ v_g,
                                        int hk, int k0, int tid) {
    int row = tid >> 2;
    int qb  = (tid & 3) * 4;
    uint32_t swr = (uint32_t)((row & 7) << 4);
    #pragma unroll
    for (int jj = 0; jj < 4; ++jj) {
        float4 kv = kg4[(size_t)(hk + k0 + row) * 16 + qb + jj];
        uint32_t h0, l0, h1, l1;
        split2(kv.x, kv.y, h0, l0);
        split2(kv.z, kv.w, h1, l1);
        uint32_t off = (uint32_t)(row * 128) + (((uint32_t)((qb + jj) * 8)) ^ swr);
        STS64(sb + SM_KHI(st) + off, pku64(h0, h1));
        STS64(sb + SM_KLO(st) + off, pku64(l0, l1));
    }
    #pragma unroll
    for (int g = 0; g < 4; ++g) {
        int task = tid + g * 256;
        int dv = task & 63;
        int kg = task >> 6;
        const float* vp = v_g + (size_t)(hk + k0 + kg * 4) * 64 + dv;
        float v0 = vp[0], v1 = vp[64], v2 = vp[128], v3 = vp[192];
        uint32_t h0, l0, h1, l1;
        split2(v0, v1, h0, l0);
        split2(v2, v3, h1, l1);
        uint32_t off = (uint32_t)(dv * 128) +
                       (((uint32_t)(kg * 8)) ^ (uint32_t)((dv & 7) << 4));
        STS64(sb + SM_VHI(st) + off, pku64(h0, h1));
        STS64(sb + SM_VLO(st) + off, pku64(l0, l1));
    }
}

__global__ void __launch_bounds__(NT, 1) attn_hmma(
    const float* __restrict__ q_g,
    const float* __restrict__ k_g,
    const float* __restrict__ v_g,
    float* __restrict__ out_g)
{
    extern __shared__ char smem[];
    const uint32_t sb = smem_u32(smem);
    float* lred = reinterpret_cast<float*>(smem + SM_LRED);
    uint32_t* mring = reinterpret_cast<uint32_t*>(smem + SM_MRING);

    const int tid  = threadIdx.x;
    const int lane = tid & 31;
    const int w    = tid >> 5;
    const bool is_compute = (w < 8);
    const int cw   = w & 7;     // role index: compute warp id / hash target warp
    const int wq   = cw & 3;    // 16-q-row group
    const int wk   = cw >> 2;   // 32-col half
    const int h  = blockIdx.y;
    const int b  = blockIdx.z;
    const int q0 = blockIdx.x * TQ;
    const int hk = h * KSK;

    // shared row identity (hash warps mirror their compute warp's lanes)
    const int rowq0 = wq * 16 + (lane >> 2);
    const int cp    = (lane & 3) * 2;
    const uint32_t hb0 = ((uint32_t)b << 26) |
                         ((uint32_t)(h * KSQ + q0 + rowq0) << 11);
    const uint32_t hb1 = hb0 + (8u << 11);

    // ---- prologue ----
    if (is_compute) {
        // stage Q (split bf16, SW128) into P region; K/V tile 0
        const float4* qg4 = reinterpret_cast<const float4*>(q_g);
        int row = tid >> 2;
        int qb  = (tid & 3) * 4;
        uint32_t swr = (uint32_t)((row & 7) << 4);
        #pragma unroll
        for (int jj = 0; jj < 4; ++jj) {
            float4 qv = qg4[((size_t)(b * KH + h) * KSQ + q0 + row) * 16 + qb + jj];
            uint32_t h0, l0, h1, l1;
            split2(qv.x, qv.y, h0, l0);
            split2(qv.z, qv.w, h1, l1);
            uint32_t off = (uint32_t)(row * 128) + (((uint32_t)((qb + jj) * 8)) ^ swr);
            STS64(sb + SM_PHI + off, pku64(h0, h1));
            STS64(sb + SM_PLO + off, pku64(l0, l1));
        }
        load_kv(sb, 0, reinterpret_cast<const float4*>(k_g), v_g, hk, 0, tid);
    } else {
        // hash warps: mask for tile 0 -> ring slot 0
        mring[0 * 256 + cw * 32 + lane] = make_mask(hb0, hb1, 0, wk, cp);
    }
    __syncthreads();

    // ---- per-lane ldmatrix addressing ----
    const int mat = lane >> 3, mr = lane & 7;
    const int arow = wq * 16 + ((mat & 1) << 3) + mr;
    const uint32_t arb = (uint32_t)(arow * 128);
    const uint32_t asw = (uint32_t)((arow & 7) << 4);
    const uint32_t akhi = (uint32_t)((mat >> 1) << 4);
    const int bn0 = wk * 32 + ((mat >> 1) << 3) + mr;
    const uint32_t brb0 = (uint32_t)(bn0 * 128);
    const uint32_t brb1 = brb0 + 16 * 128;
    const uint32_t bsw = (uint32_t)((bn0 & 7) << 4);
    const uint32_t bkhi = (uint32_t)((mat & 1) << 4);

    // ---- Q fragments, loaded once (compute warps only) ----
    uint32_t qh[4][4], ql[4][4];
    if (is_compute) {
        #pragma unroll
        for (int ch = 0; ch < 4; ++ch) {
            uint32_t kb = ((uint32_t)(ch * 32) + akhi) ^ asw;
            LDMX4(qh[ch], sb + SM_PHI + arb + kb);
            LDMX4(ql[ch], sb + SM_PLO + arb + kb);
        }
    }

    float o[4][4];
    #pragma unroll
    for (int nt = 0; nt < 4; ++nt)
        #pragma unroll
        for (int i = 0; i < 4; ++i) o[nt][i] = 0.f;
    float lp0 = 0.f, lp1 = 0.f;

    const uint32_t psw  = (uint32_t)((rowq0 & 7) << 4);
    const uint32_t prb0 = (uint32_t)(rowq0 * 128);
    const uint32_t prb1 = prb0 + 8 * 128;
    const uint32_t pcb  = (uint32_t)(wk * 64 + cp * 2);

    const float4* kg4 = reinterpret_cast<const float4*>(k_g);

    for (int kt = 0; kt < NTILES; ++kt) {
        const int cur = kt & 1;

        uint32_t ph01[4], pl01[4], ph23[4], pl23[4];
        if (is_compute) {
            // ---- [A] S = Q K^T (split: hh + hl + lh) ----
            float s[4][4];
            #pragma unroll
            for (int nt = 0; nt < 4; ++nt)
                #pragma unroll
                for (int i = 0; i < 4; ++i) s[nt][i] = 0.f;

            #pragma unroll
            for (int ch = 0; ch < 4; ++ch) {
                uint32_t kb = ((uint32_t)(ch * 32) + bkhi) ^ bsw;
                uint32_t bh0[4], bl0[4], bh1[4], bl1[4];
                LDMX4(bh0, sb + SM_KHI(cur) + brb0 + kb);
                LDMX4(bl0, sb + SM_KLO(cur) + brb0 + kb);
                LDMX4(bh1, sb + SM_KHI(cur) + brb1 + kb);
                LDMX4(bl1, sb + SM_KLO(cur) + brb1 + kb);
                MMA16816(s[0], qh[ch], bh0[0], bh0[1]);
                MMA16816(s[0], qh[ch], bl0[0], bl0[1]);
                MMA16816(s[0], ql[ch], bh0[0], bh0[1]);
                MMA16816(s[1], qh[ch], bh0[2], bh0[3]);
                MMA16816(s[1], qh[ch], bl0[2], bl0[3]);
                MMA16816(s[1], ql[ch], bh0[2], bh0[3]);
                MMA16816(s[2], qh[ch], bh1[0], bh1[1]);
                MMA16816(s[2], qh[ch], bl1[0], bl1[1]);
                MMA16816(s[2], ql[ch], bh1[0], bh1[1]);
                MMA16816(s[3], qh[ch], bh1[2], bh1[3]);
                MMA16816(s[3], qh[ch], bl1[2], bl1[3]);
                MMA16816(s[3], ql[ch], bh1[2], bh1[3]);
            }

            // ---- [B] exp + masked select (mask from ring) + pack P ----
            uint32_t mask = mring[cur * 256 + cw * 32 + lane];
            #pragma unroll
            for (int nt = 0; nt < 4; ++nt) {
                uint32_t mb = mask >> (nt * 4);
                float e0 = ex2f(fmaf(s[nt][0], L2E, NEGC));
                float e1 = ex2f(fmaf(s[nt][1], L2E, NEGC));
                float e2 = ex2f(fmaf(s[nt][2], L2E, NEGC));
                float e3 = ex2f(fmaf(s[nt][3], L2E, NEGC));
                lp0 += e0 + e1;
                lp1 += e2 + e3;
                float p0 = (mb & 1u) ? e0 : 0.f;
                float p1 = (mb & 2u) ? e1 : 0.f;
                float p2 = (mb & 4u) ? e2 : 0.f;
                float p3 = (mb & 8u) ? e3 : 0.f;
                split2(p0, p1, ph01[nt], pl01[nt]);
                split2(p2, p3, ph23[nt], pl23[nt]);
            }
        } else {
            // ---- hash warps: produce mask for tile kt+1 ----
            if (kt + 1 < NTILES)
                mring[((kt + 1) & 1) * 256 + cw * 32 + lane] =
                    make_mask(hb0, hb1, (kt + 1) * 64, wk, cp);
        }

        __syncthreads();   // [C] prev PV done with P; masks(kt+1) published

        if (is_compute) {
            // ---- [D] store P; prefetch next K/V tile ----
            #pragma unroll
            for (int nt = 0; nt < 4; ++nt) {
                uint32_t co = (pcb + (uint32_t)(nt * 16)) ^ psw;
                STS32(sb + SM_PHI + prb0 + co, ph01[nt]);
                STS32(sb + SM_PLO + prb0 + co, pl01[nt]);
                STS32(sb + SM_PHI + prb1 + co, ph23[nt]);
                STS32(sb + SM_PLO + prb1 + co, pl23[nt]);
            }
            if (kt + 1 < NTILES)
                load_kv(sb, cur ^ 1, kg4, v_g, hk, (kt + 1) * TK, tid);
        }

        __syncthreads();   // [E] P and KV visible

        if (is_compute) {
            // ---- [F] O += P V   (split: hh + hl + lh) ----
            #pragma unroll
            for (int ch = 0; ch < 4; ++ch) {
                uint32_t akb = ((uint32_t)(ch * 32) + akhi) ^ asw;
                uint32_t ah[4], al[4];
                LDMX4(ah, sb + SM_PHI + arb + akb);
                LDMX4(al, sb + SM_PLO + arb + akb);
                uint32_t kb = ((uint32_t)(ch * 32) + bkhi) ^ bsw;
                uint32_t bh0[4], bl0[4], bh1[4], bl1[4];
                LDMX4(bh0, sb + SM_VHI(cur) + brb0 + kb);
                LDMX4(bl0, sb + SM_VLO(cur) + brb0 + kb);
                LDMX4(bh1, sb + SM_VHI(cur) + brb1 + kb);
                LDMX4(bl1, sb + SM_VLO(cur) + brb1 + kb);
                MMA16816(o[0], ah, bh0[0], bh0[1]);
                MMA16816(o[0], ah, bl0[0], bl0[1]);
                MMA16816(o[0], al, bh0[0], bh0[1]);
                MMA16816(o[1], ah, bh0[2], bh0[3]);
                MMA16816(o[1], ah, bl0[2], bl0[3]);
                MMA16816(o[1], al, bh0[2], bh0[3]);
                MMA16816(o[2], ah, bh1[0], bh1[1]);
                MMA16816(o[2], ah, bl1[0], bl1[1]);
                MMA16816(o[2], al, bh1[0], bh1[1]);
                MMA16816(o[3], ah, bh1[2], bh1[3]);
                MMA16816(o[3], ah, bl1[2], bl1[3]);
                MMA16816(o[3], al, bh1[2], bh1[3]);
            }
        }
    }

    // ---- l reduction (compute warps) ----
    if (is_compute) {
        lp0 += __shfl_xor_sync(0xffffffffu, lp0, 1);
        lp0 += __shfl_xor_sync(0xffffffffu, lp0, 2);
        lp1 += __shfl_xor_sync(0xffffffffu, lp1, 1);
        lp1 += __shfl_xor_sync(0xffffffffu, lp1, 2);
        if ((lane & 3) == 0) {
            lred[wk * 64 + rowq0]     = lp0;
            lred[wk * 64 + rowq0 + 8] = lp1;
        }
    }
    __syncthreads();
    if (is_compute) {
        const float fin = 0.5f / 0.9f;
        const float sc0 = fin / (lred[rowq0]     + lred[64 + rowq0]);
        const float sc1 = fin / (lred[rowq0 + 8] + lred[64 + rowq0 + 8]);

        float2* out2 = reinterpret_cast<float2*>(out_g);
        const size_t ob0 = ((size_t)(b * KH + h) * KSQ + q0 + rowq0) * 32;
        #pragma unroll
        for (int nt = 0; nt < 4; ++nt) {
            int c2 = (wk * 32 + nt * 8 + cp) >> 1;
            out2[ob0 + c2] = make_float2(o[nt][0] * sc0, o[nt][1] * sc0);
            out2[ob0 + 8 * 32 + c2] = make_float2(o[nt][2] * sc1, o[nt][3] * sc1);
        }
    }
}

extern "C" void kernel_launch(void* const* d_in, const int* in_sizes, int n_in,
                              void* d_out, int out_size) {
    (void)in_sizes; (void)n_in; (void)out_size;
    const float* q = (const float*)d_in[0];
    const float* k = (const float*)d_in[1];
    const float* v = (const float*)d_in[2];
    float* out = (float*)d_out;

    cudaFuncSetAttribute(attn_hmma,
                         cudaFuncAttributeMaxDynamicSharedMemorySize, SMEM_BYTES);
    dim3 grid(KSQ / TQ, KH, KB);   // (32, 16, 2) = 1024 CTAs
    attn_hmma<<<grid, NT, SMEM_BYTES>>>(q, k, v, out);
}

// round 15
// speedup vs baseline: 1.0063x; 1.0063x over previous
#include <cuda_runtime.h>
#include <cuda_bf16.h>
#include <cstdint>

#define KB   2
#define KH   16
#define KSQ  2048
#define KSK  2048
#define TQ   64
#define TK   64
#define NT   256
#define NTILES (KSK / TK)

#define KEEP_THRESH 0xE6666600u      // jax uniform(bits) < 0.9f
#define L2E  1.4426950408889634f
#define NEGC (-30.0f * 1.4426950408889634f)   // fixed shift C=30 in log2 units

// ---- smem byte offsets (R11 layout: Q in dedicated region, P separate) ----
#define SM_PHI   0
#define SM_PLO   8192
#define SM_KHI(s) (16384 + (s)*16384)
#define SM_KLO(s) (16384 + (s)*16384 + 8192)
#define SM_VHI(s) (49152 + (s)*16384)
#define SM_VLO(s) (49152 + (s)*16384 + 8192)
#define SM_LRED  81920        // 128 floats
#define SM_QHI   82432
#define SM_QLO   90624
#define SMEM_BYTES 98816

__device__ __forceinline__ uint32_t smem_u32(const void* p) {
    uint32_t a;
    asm("{ .reg .u64 t; cvta.to.shared.u64 t, %1; cvt.u32.u64 %0, t; }"
        : "=r"(a) : "l"(p));
    return a;
}
__device__ __forceinline__ unsigned long long pku64(uint32_t lo, uint32_t hi) {
    unsigned long long r;
    asm("mov.b64 %0, {%1, %2};" : "=l"(r) : "r"(lo), "r"(hi));
    return r;
}
#define STS64(addr, v) \
    asm volatile("st.shared.b64 [%0], %1;" :: "r"(addr), "l"(v) : "memory")
#define STS32(addr, v) \
    asm volatile("st.shared.b32 [%0], %1;" :: "r"(addr), "r"(v) : "memory")
__device__ __forceinline__ float ex2f(float x) {
    float r; asm("ex2.approx.f32 %0, %1;" : "=f"(r) : "f"(x)); return r;
}
// split floats a,b -> bf16x2 hi (a low half) + bf16x2 lo residual
__device__ __forceinline__ void split2(float a, float b, uint32_t& hi, uint32_t& lo) {
    uint32_t h;
    asm("cvt.rn.bf16x2.f32 %0, %1, %2;" : "=r"(h) : "f"(b), "f"(a));
    float ha = __uint_as_float(h << 16);
    float hb = __uint_as_float(h & 0xFFFF0000u);
    float la = a - ha, lb = b - hb;
    uint32_t l;
    asm("cvt.rn.bf16x2.f32 %0, %1, %2;" : "=r"(l) : "f"(lb), "f"(la));
    hi = h; lo = l;
}

#define LDMX4(r, addr) \
    asm volatile("ldmatrix.sync.aligned.m8n8.x4.shared.b16 {%0,%1,%2,%3}, [%4];" \
        : "=r"((r)[0]), "=r"((r)[1]), "=r"((r)[2]), "=r"((r)[3]) : "r"(addr))

#define MMA16816(d, a, b0, b1) \
    asm volatile("mma.sync.aligned.m16n8k16.row.col.f32.bf16.bf16.f32 " \
        "{%0,%1,%2,%3}, {%4,%5,%6,%7}, {%8,%9}, {%0,%1,%2,%3};" \
        : "+f"((d)[0]), "+f"((d)[1]), "+f"((d)[2]), "+f"((d)[3]) \
        : "r"((a)[0]), "r"((a)[1]), "r"((a)[2]), "r"((a)[3]), "r"(b0), "r"(b1))

// JAX partitionable threefry, key=(0,42): bits = y0 ^ y1  (bit-exact, R6 form)
__device__ __forceinline__ uint32_t tf32_hash(uint32_t idx) {
    const uint32_t ks1 = 42u;
    const uint32_t ks2 = 42u ^ 0x1BD11BDAu;
    uint32_t x0 = 0u;
    uint32_t x1 = idx + ks1;
#define TFR(r) { x0 += x1; x1 = __funnelshift_l(x1, x1, (r)); x1 ^= x0; }
    TFR(13) TFR(15) TFR(26) TFR(6)
    x0 += ks1; x1 += ks2 + 1u;
    TFR(17) TFR(29) TFR(16) TFR(24)
    x0 += ks2; x1 += 2u;
    TFR(13) TFR(15) TFR(26) TFR(6)
    x1 += ks1 + 3u;
    TFR(17) TFR(29) TFR(16) TFR(24)
    x0 += ks1; x1 += ks2 + 4u;
    TFR(13) TFR(15) TFR(26) TFR(6)
    x0 += ks2; x1 += 5u;
#undef TFR
    return x0 ^ x1;
}

// prologue-only: K/V tile 0 -> split bf16 smem (direct LDG->STS)
__device__ __forceinline__ void load_kv0(uint32_t sb,
                                         const float4* __restrict__ kg4,
                                         const float* __restrict__ v_g,
                                         int hk, int tid) {
    int row = tid >> 2;
    int qb  = (tid & 3) * 4;
    uint32_t swr = (uint32_t)((row & 7) << 4);
    #pragma unroll
    for (int jj = 0; jj < 4; ++jj) {
        float4 kv = kg4[(size_t)(hk + row) * 16 + qb + jj];
        uint32_t h0, l0, h1, l1;
        split2(kv.x, kv.y, h0, l0);
        split2(kv.z, kv.w, h1, l1);
        uint32_t off = (uint32_t)(row * 128) + (((uint32_t)((qb + jj) * 8)) ^ swr);
        STS64(sb + SM_KHI(0) + off, pku64(h0, h1));
        STS64(sb + SM_KLO(0) + off, pku64(l0, l1));
    }
    #pragma unroll
    for (int g = 0; g < 2; ++g) {
        int task = tid + g * NT;          // 0..511
        int kp = task >> 4;               // k-pair 0..31
        int dq = (task & 15) * 4;         // dv quad base
        const float4* vp = reinterpret_cast<const float4*>(
            v_g + (size_t)(hk + kp * 2) * 64 + dq);
        float4 vA = vp[0], vB = vp[16];
        uint32_t h, l;
        uint32_t cb = (uint32_t)(kp * 4);
        split2(vA.x, vB.x, h, l);
        { uint32_t o = (uint32_t)(dq * 128) + (cb ^ (uint32_t)((dq & 7) << 4));
          STS32(sb + SM_VHI(0) + o, h); STS32(sb + SM_VLO(0) + o, l); }
        split2(vA.y, vB.y, h, l);
        { int d = dq + 1; uint32_t o = (uint32_t)(d * 128) + (cb ^ (uint32_t)((d & 7) << 4));
          STS32(sb + SM_VHI(0) + o, h); STS32(sb + SM_VLO(0) + o, l); }
        split2(vA.z, vB.z, h, l);
        { int d = dq + 2; uint32_t o = (uint32_t)(d * 128) + (cb ^ (uint32_t)((d & 7) << 4));
          STS32(sb + SM_VHI(0) + o, h); STS32(sb + SM_VLO(0) + o, l); }
        split2(vA.w, vB.w, h, l);
        { int d = dq + 3; uint32_t o = (uint32_t)(d * 128) + (cb ^ (uint32_t)((d & 7) << 4));
          STS32(sb + SM_VHI(0) + o, h); STS32(sb + SM_VLO(0) + o, l); }
    }
}

__global__ void __launch_bounds__(NT, 2) attn_hmma(
    const float* __restrict__ q_g,
    const float* __restrict__ k_g,
    const float* __restrict__ v_g,
    float* __restrict__ out_g)
{
    extern __shared__ char smem[];
    const uint32_t sb = smem_u32(smem);
    float* lred = reinterpret_cast<float*>(smem + SM_LRED);

    const int tid  = threadIdx.x;
    const int lane = tid & 31;
    const int w    = tid >> 5;
    const int wq   = w & 3;     // 16-q-row group
    const int wk   = w >> 2;    // 32-col half (k for QK, dv for PV)
    const int h  = blockIdx.y;
    const int b  = blockIdx.z;
    const int q0 = blockIdx.x * TQ;
    const int hk = h * KSK;

    // ---- prologue: stage Q (split bf16, SW128) into its OWN region; K/V tile 0 ----
    {
        const float4* qg4 = reinterpret_cast<const float4*>(q_g);
        int row = tid >> 2;
        int qb  = (tid & 3) * 4;
        uint32_t swr = (uint32_t)((row & 7) << 4);
        #pragma unroll
        for (int jj = 0; jj < 4; ++jj) {
            float4 qv = qg4[((size_t)(b * KH + h) * KSQ + q0 + row) * 16 + qb + jj];
            uint32_t h0, l0, h1, l1;
            split2(qv.x, qv.y, h0, l0);
            split2(qv.z, qv.w, h1, l1);
            uint32_t off = (uint32_t)(row * 128) + (((uint32_t)((qb + jj) * 8)) ^ swr);
            STS64(sb + SM_QHI + off, pku64(h0, h1));
            STS64(sb + SM_QLO + off, pku64(l0, l1));
        }
    }
    load_kv0(sb, reinterpret_cast<const float4*>(k_g), v_g, hk, tid);
    __syncthreads();

    // ---- per-lane ldmatrix addressing ----
    const int mat = lane >> 3, mr = lane & 7;
    const int arow = wq * 16 + ((mat & 1) << 3) + mr;       // A frag row
    const uint32_t arb = (uint32_t)(arow * 128);
    const uint32_t asw = (uint32_t)((arow & 7) << 4);
    const uint32_t akhi = (uint32_t)((mat >> 1) << 4);      // A k-byte half
    const int bn0 = wk * 32 + ((mat >> 1) << 3) + mr;       // B frag row (= n)
    const uint32_t brb0 = (uint32_t)(bn0 * 128);
    const uint32_t brb1 = brb0 + 16 * 128;
    const uint32_t bsw = (uint32_t)((bn0 & 7) << 4);
    const uint32_t bkhi = (uint32_t)((mat & 1) << 4);       // B k-byte half

    float o[4][4];
    #pragma unroll
    for (int nt = 0; nt < 4; ++nt)
        #pragma unroll
        for (int i = 0; i < 4; ++i) o[nt][i] = 0.f;
    float lp0 = 0.f, lp1 = 0.f;

    const int rowq0 = wq * 16 + (lane >> 2);          // score/output row (and +8)
    const int cp    = (lane & 3) * 2;                 // col-pair within 8
    const uint32_t hb0 = ((uint32_t)b << 26) |
                         ((uint32_t)(h * KSQ + q0 + rowq0) << 11);
    const uint32_t hb1 = hb0 + (8u << 11);
    const uint32_t psw  = (uint32_t)((rowq0 & 7) << 4);   // same for rowq0+8
    const uint32_t prb0 = (uint32_t)(rowq0 * 128);
    const uint32_t prb1 = prb0 + 8 * 128;
    const uint32_t pcb  = (uint32_t)(wk * 64 + cp * 2);   // P col byte base

    // gmem load addressing for hoisted prefetch
    const int krow = tid >> 2;
    const int kqb  = (tid & 3) * 4;
    const uint32_t kswr = (uint32_t)((krow & 7) << 4);
    const int vkp0 = tid >> 4;            // task g=0 k-pair
    const int vdq  = (tid & 15) * 4;      // dv quad (same both tasks)
    const float4* kg4 = reinterpret_cast<const float4*>(k_g);

    for (int kt = 0; kt < NTILES; ++kt) {
        const int cur = kt & 1;
        const int knext = (kt + 1 < NTILES) ? (kt + 1) * TK : 0;

        // ---- hoisted LDGs for tile kt+1 (latency hidden under [A]+[B]) ----
        float4 kr[4], vA[2], vB[2];
        #pragma unroll
        for (int jj = 0; jj < 4; ++jj)
            kr[jj] = kg4[(size_t)(hk + knext + krow) * 16 + kqb + jj];
        #pragma unroll
        for (int g = 0; g < 2; ++g) {
            const float4* vp = reinterpret_cast<const float4*>(
                v_g + (size_t)(hk + knext + (vkp0 + g * 16) * 2) * 64 + vdq);
            vA[g] = vp[0]; vB[g] = vp[16];
        }

        // ---- [A] S = Q K^T (split: hh + hl + lh); Q frags from smem ----
        float s[4][4];
        #pragma unroll
        for (int nt = 0; nt < 4; ++nt)
            #pragma unroll
            for (int i = 0; i < 4; ++i) s[nt][i] = 0.f;

        #pragma unroll
        for (int ch = 0; ch < 4; ++ch) {
            uint32_t qkb = ((uint32_t)(ch * 32) + akhi) ^ asw;
            uint32_t qh[4], ql[4];
            LDMX4(qh, sb + SM_QHI + arb + qkb);
            LDMX4(ql, sb + SM_QLO + arb + qkb);
            uint32_t kb = ((uint32_t)(ch * 32) + bkhi) ^ bsw;
            uint32_t bh0[4], bl0[4], bh1[4], bl1[4];
            LDMX4(bh0, sb + SM_KHI(cur) + brb0 + kb);
            LDMX4(bl0, sb + SM_KLO(cur) + brb0 + kb);
            LDMX4(bh1, sb + SM_KHI(cur) + brb1 + kb);
            LDMX4(bl1, sb + SM_KLO(cur) + brb1 + kb);
            MMA16816(s[0], qh, bh0[0], bh0[1]);
            MMA16816(s[0], qh, bl0[0], bl0[1]);
            MMA16816(s[0], ql, bh0[0], bh0[1]);
            MMA16816(s[1], qh, bh0[2], bh0[3]);
            MMA16816(s[1], qh, bl0[2], bl0[3]);
            MMA16816(s[1], ql, bh0[2], bh0[3]);
            MMA16816(s[2], qh, bh1[0], bh1[1]);
            MMA16816(s[2], qh, bl1[0], bl1[1]);
            MMA16816(s[2], ql, bh1[0], bh1[1]);
            MMA16816(s[3], qh, bh1[2], bh1[3]);
            MMA16816(s[3], qh, bl1[2], bl1[3]);
            MMA16816(s[3], ql, bh1[2], bh1[3]);
        }

        // ---- [B] exp + dropout mask + pack P (R6 form, hash inline) ----
        uint32_t ph01[4], pl01[4], ph23[4], pl23[4];
        const uint32_t kb0 = hb0 | (uint32_t)(kt * 64 + wk * 32);
        const uint32_t kb1 = hb1 | (uint32_t)(kt * 64 + wk * 32);
        #pragma unroll
        for (int nt = 0; nt < 4; ++nt) {
            uint32_t colw = (uint32_t)(nt * 8 + cp);
            float e0 = ex2f(fmaf(s[nt][0], L2E, NEGC));
            float e1 = ex2f(fmaf(s[nt][1], L2E, NEGC));
            float e2 = ex2f(fmaf(s[nt][2], L2E, NEGC));
            float e3 = ex2f(fmaf(s[nt][3], L2E, NEGC));
            lp0 += e0 + e1;
            lp1 += e2 + e3;
            float p0 = (tf32_hash(kb0 + colw)      < KEEP_THRESH) ? e0 : 0.f;
            float p1 = (tf32_hash(kb0 + colw + 1u) < KEEP_THRESH) ? e1 : 0.f;
            float p2 = (tf32_hash(kb1 + colw)      < KEEP_THRESH) ? e2 : 0.f;
            float p3 = (tf32_hash(kb1 + colw + 1u) < KEEP_THRESH) ? e3 : 0.f;
            split2(p0, p1, ph01[nt], pl01[nt]);
            split2(p2, p3, ph23[nt], pl23[nt]);
        }

        __syncthreads();   // [C] prev PV done reading P; next KV stage free

        // ---- [D] store P; store prefetched K/V into stage cur^1 (pure STS) ----
        #pragma unroll
        for (int nt = 0; nt < 4; ++nt) {
            uint32_t co = (pcb + (uint32_t)(nt * 16)) ^ psw;
            STS32(sb + SM_PHI + prb0 + co, ph01[nt]);
            STS32(sb + SM_PLO + prb0 + co, pl01[nt]);
            STS32(sb + SM_PHI + prb1 + co, ph23[nt]);
            STS32(sb + SM_PLO + prb1 + co, pl23[nt]);
        }
        if (kt + 1 < NTILES) {
            const int nst = cur ^ 1;
            #pragma unroll
            for (int jj = 0; jj < 4; ++jj) {
                uint32_t h0, l0, h1, l1;
                split2(kr[jj].x, kr[jj].y, h0, l0);
                split2(kr[jj].z, kr[jj].w, h1, l1);
                uint32_t off = (uint32_t)(krow * 128) +
                               (((uint32_t)((kqb + jj) * 8)) ^ kswr);
                STS64(sb + SM_KHI(nst) + off, pku64(h0, h1));
                STS64(sb + SM_KLO(nst) + off, pku64(l0, l1));
            }
            #pragma unroll
            for (int g = 0; g < 2; ++g) {
                uint32_t cb = (uint32_t)((vkp0 + g * 16) * 4);
                uint32_t hh, ll;
                split2(vA[g].x, vB[g].x, hh, ll);
                { uint32_t oo = (uint32_t)(vdq * 128) + (cb ^ (uint32_t)((vdq & 7) << 4));
                  STS32(sb + SM_VHI(nst) + oo, hh); STS32(sb + SM_VLO(nst) + oo, ll); }
                split2(vA[g].y, vB[g].y, hh, ll);
                { int d = vdq + 1; uint32_t oo = (uint32_t)(d * 128) + (cb ^ (uint32_t)((d & 7) << 4));
                  STS32(sb + SM_VHI(nst) + oo, hh); STS32(sb + SM_VLO(nst) + oo, ll); }
                split2(vA[g].z, vB[g].z, hh, ll);
                { int d = vdq + 2; uint32_t oo = (uint32_t)(d * 128) + (cb ^ (uint32_t)((d & 7) << 4));
                  STS32(sb + SM_VHI(nst) + oo, hh); STS32(sb + SM_VLO(nst) + oo, ll); }
                split2(vA[g].w, vB[g].w, hh, ll);
                { int d = vdq + 3; uint32_t oo = (uint32_t)(d * 128) + (cb ^ (uint32_t)((d & 7) << 4));
                  STS32(sb + SM_VHI(nst) + oo, hh); STS32(sb + SM_VLO(nst) + oo, ll); }
            }
        }

        __syncthreads();   // [E] P and next K/V visible

        // ---- [F] O += P V   (split: hh + hl + lh) ----
        #pragma unroll
        for (int ch = 0; ch < 4; ++ch) {
            uint32_t akb = ((uint32_t)(ch * 32) + akhi) ^ asw;
            uint32_t ah[4], al[4];
            LDMX4(ah, sb + SM_PHI + arb + akb);
            LDMX4(al, sb + SM_PLO + arb + akb);
            uint32_t kb = ((uint32_t)(ch * 32) + bkhi) ^ bsw;
            uint32_t bh0[4], bl0[4], bh1[4], bl1[4];
            LDMX4(bh0, sb + SM_VHI(cur) + brb0 + kb);
            LDMX4(bl0, sb + SM_VLO(cur) + brb0 + kb);
            LDMX4(bh1, sb + SM_VHI(cur) + brb1 + kb);
            LDMX4(bl1, sb + SM_VLO(cur) + brb1 + kb);
            MMA16816(o[0], ah, bh0[0], bh0[1]);
            MMA16816(o[0], ah, bl0[0], bl0[1]);
            MMA16816(o[0], al, bh0[0], bh0[1]);
            MMA16816(o[1], ah, bh0[2], bh0[3]);
            MMA16816(o[1], ah, bl0[2], bl0[3]);
            MMA16816(o[1], al, bh0[2], bh0[3]);
            MMA16816(o[2], ah, bh1[0], bh1[1]);
            MMA16816(o[2], ah, bl1[0], bl1[1]);
            MMA16816(o[2], al, bh1[0], bh1[1]);
            MMA16816(o[3], ah, bh1[2], bh1[3]);
            MMA16816(o[3], ah, bl1[2], bl1[3]);
            MMA16816(o[3], al, bh1[2], bh1[3]);
        }
    }

    // ---- l reduction: butterfly over the 4 col-lanes, combine 2 warp-halves ----
    lp0 += __shfl_xor_sync(0xffffffffu, lp0, 1);
    lp0 += __shfl_xor_sync(0xffffffffu, lp0, 2);
    lp1 += __shfl_xor_sync(0xffffffffu, lp1, 1);
    lp1 += __shfl_xor_sync(0xffffffffu, lp1, 2);
    if ((lane & 3) == 0) {
        lred[wk * 64 + rowq0]     = lp0;
        lred[wk * 64 + rowq0 + 8] = lp1;
    }
    __syncthreads();
    const float fin = 0.5f / 0.9f;
    const float sc0 = fin / (lred[rowq0]     + lred[64 + rowq0]);
    const float sc1 = fin / (lred[rowq0 + 8] + lred[64 + rowq0 + 8]);

    // ---- epilogue ----
    float2* out2 = reinterpret_cast<float2*>(out_g);
    const size_t ob0 = ((size_t)(b * KH + h) * KSQ + q0 + rowq0) * 32;
    #pragma unroll
    for (int nt = 0; nt < 4; ++nt) {
        int c2 = (wk * 32 + nt * 8 + cp) >> 1;
        out2[ob0 + c2] = make_float2(o[nt][0] * sc0, o[nt][1] * sc0);
        out2[ob0 + 8 * 32 + c2] = make_float2(o[nt][2] * sc1, o[nt][3] * sc1);
    }
}

extern "C" void kernel_launch(void* const* d_in, const int* in_sizes, int n_in,
                              void* d_out, int out_size) {
    (void)in_sizes; (void)n_in; (void)out_size;
    const float* q = (const float*)d_in[0];
    const float* k = (const float*)d_in[1];
    const float* v = (const float*)d_in[2];
    float* out = (float*)d_out;

    cudaFuncSetAttribute(attn_hmma,
                         cudaFuncAttributeMaxDynamicSharedMemorySize, SMEM_BYTES);
    dim3 grid(KSQ / TQ, KH, KB);   // (32, 16, 2) = 1024 CTAs
    attn_hmma<<<grid, NT, SMEM_BYTES>>>(q, k, v, out);
}

// round 16
// speedup vs baseline: 1.1332x; 1.1261x over previous
#include <cuda_runtime.h>
#include <cuda_bf16.h>
#include <cstdint>

#define KB   2
#define KH   16
#define KSQ  2048
#define KSK  2048
#define TQ   64
#define TK   64
#define NT   256
#define NTILES (KSK / TK)

#define KEEP_THRESH 0xE6666600u      // jax uniform(bits) < 0.9f
#define L2E  1.4426950408889634f
#define NEGC (-30.0f * 1.4426950408889634f)   // fixed shift C=30 in log2 units

// ---- smem byte offsets (R11 layout: Q in dedicated region) ----
#define SM_PHI   0
#define SM_PLO   8192
#define SM_KHI(s) (16384 + (s)*16384)
#define SM_KLO(s) (16384 + (s)*16384 + 8192)
#define SM_VHI(s) (49152 + (s)*16384)
#define SM_VLO(s) (49152 + (s)*16384 + 8192)
#define SM_LRED  81920        // 128 floats
#define SM_QHI   82432
#define SM_QLO   90624
#define SMEM_BYTES 98816

__device__ __forceinline__ uint32_t smem_u32(const void* p) {
    uint32_t a;
    asm("{ .reg .u64 t; cvta.to.shared.u64 t, %1; cvt.u32.u64 %0, t; }"
        : "=r"(a) : "l"(p));
    return a;
}
__device__ __forceinline__ unsigned long long pku64(uint32_t lo, uint32_t hi) {
    unsigned long long r;
    asm("mov.b64 %0, {%1, %2};" : "=l"(r) : "r"(lo), "r"(hi));
    return r;
}
#define STS64(addr, v) \
    asm volatile("st.shared.b64 [%0], %1;" :: "r"(addr), "l"(v) : "memory")
#define STS32(addr, v) \
    asm volatile("st.shared.b32 [%0], %1;" :: "r"(addr), "r"(v) : "memory")
__device__ __forceinline__ float ex2f(float x) {
    float r; asm("ex2.approx.f32 %0, %1;" : "=f"(r) : "f"(x)); return r;
}
// split floats a,b -> bf16x2 hi (a low half) + bf16x2 lo residual
__device__ __forceinline__ void split2(float a, float b, uint32_t& hi, uint32_t& lo) {
    uint32_t h;
    asm("cvt.rn.bf16x2.f32 %0, %1, %2;" : "=r"(h) : "f"(b), "f"(a));
    float ha = __uint_as_float(h << 16);
    float hb = __uint_as_float(h & 0xFFFF0000u);
    float la = a - ha, lb = b - hb;
    uint32_t l;
    asm("cvt.rn.bf16x2.f32 %0, %1, %2;" : "=r"(l) : "f"(lb), "f"(la));
    hi = h; lo = l;
}

#define LDMX4(r, addr) \
    asm volatile("ldmatrix.sync.aligned.m8n8.x4.shared.b16 {%0,%1,%2,%3}, [%4];" \
        : "=r"((r)[0]), "=r"((r)[1]), "=r"((r)[2]), "=r"((r)[3]) : "r"(addr))

#define MMA16816(d, a, b0, b1) \
    asm volatile("mma.sync.aligned.m16n8k16.row.col.f32.bf16.bf16.f32 " \
        "{%0,%1,%2,%3}, {%4,%5,%6,%7}, {%8,%9}, {%0,%1,%2,%3};" \
        : "+f"((d)[0]), "+f"((d)[1]), "+f"((d)[2]), "+f"((d)[3]) \
        : "r"((a)[0]), "r"((a)[1]), "r"((a)[2]), "r"((a)[3]), "r"(b0), "r"(b1))

// JAX partitionable threefry, key=(0,42): bits = y0 ^ y1  (bit-exact).
// 4 independent hashes computed in LOCKSTEP: every round issues 4x IADD,
// 4x SHF, 4x LOP3 on independent registers, covering the lat-4 dependency
// chain within a single warp. (The serial per-call form capped the alu pipe
// at ~0.5 op/cyc/warp -> the measured 52-58% alu duty across R6-R15.)
__device__ __forceinline__ void tf32_hash4(
    uint32_t i0, uint32_t i1, uint32_t i2, uint32_t i3,
    uint32_t& o0, uint32_t& o1, uint32_t& o2, uint32_t& o3)
{
    const uint32_t ks1 = 42u;
    const uint32_t ks2 = 42u ^ 0x1BD11BDAu;
    uint32_t a0 = 0u, b0_ = i0 + ks1;
    uint32_t a1 = 0u, b1_ = i1 + ks1;
    uint32_t a2 = 0u, b2_ = i2 + ks1;
    uint32_t a3 = 0u, b3_ = i3 + ks1;
#define TFR4(r) { \
    a0 += b0_; a1 += b1_; a2 += b2_; a3 += b3_; \
    b0_ = __funnelshift_l(b0_, b0_, (r)); \
    b1_ = __funnelshift_l(b1_, b1_, (r)); \
    b2_ = __funnelshift_l(b2_, b2_, (r)); \
    b3_ = __funnelshift_l(b3_, b3_, (r)); \
    b0_ ^= a0; b1_ ^= a1; b2_ ^= a2; b3_ ^= a3; }
#define KEY4(ka, kb) { \
    a0 += (ka); a1 += (ka); a2 += (ka); a3 += (ka); \
    b0_ += (kb); b1_ += (kb); b2_ += (kb); b3_ += (kb); }
    TFR4(13) TFR4(15) TFR4(26) TFR4(6)
    KEY4(ks1, ks2 + 1u)
    TFR4(17) TFR4(29) TFR4(16) TFR4(24)
    KEY4(ks2, 2u)
    TFR4(13) TFR4(15) TFR4(26) TFR4(6)
    KEY4(0u, ks1 + 3u)
    TFR4(17) TFR4(29) TFR4(16) TFR4(24)
    KEY4(ks1, ks2 + 4u)
    TFR4(13) TFR4(15) TFR4(26) TFR4(6)
    KEY4(ks2, 5u)
#undef TFR4
#undef KEY4
    o0 = a0 ^ b0_;
    o1 = a1 ^ b1_;
    o2 = a2 ^ b2_;
    o3 = a3 ^ b3_;
}

// K tile [64k][64d] and V^T tile [64dv][64k] -> split bf16, SW128 rows (128B)
__device__ __forceinline__ void load_kv(uint32_t sb, int st,
                                        const float4* __restrict__ kg4,
                                        const float* __restrict__ v_g,
                                        int hk, int k0, int tid) {
    int row = tid >> 2;
    int qb  = (tid & 3) * 4;
    uint32_t swr = (uint32_t)((row & 7) << 4);
    #pragma unroll
    for (int jj = 0; jj < 4; ++jj) {
        float4 kv = kg4[(size_t)(hk + k0 + row) * 16 + qb + jj];
        uint32_t h0, l0, h1, l1;
        split2(kv.x, kv.y, h0, l0);
        split2(kv.z, kv.w, h1, l1);
        uint32_t off = (uint32_t)(row * 128) + (((uint32_t)((qb + jj) * 8)) ^ swr);
        STS64(sb + SM_KHI(st) + off, pku64(h0, h1));
        STS64(sb + SM_KLO(st) + off, pku64(l0, l1));
    }
    #pragma unroll
    for (int g = 0; g < 4; ++g) {
        int task = tid + g * NT;
        int dv = task & 63;
        int kg = task >> 6;
        const float* vp = v_g + (size_t)(hk + k0 + kg * 4) * 64 + dv;
        float v0 = vp[0], v1 = vp[64], v2 = vp[128], v3 = vp[192];
        uint32_t h0, l0, h1, l1;
        split2(v0, v1, h0, l0);
        split2(v2, v3, h1, l1);
        uint32_t off = (uint32_t)(dv * 128) +
                       (((uint32_t)(kg * 8)) ^ (uint32_t)((dv & 7) << 4));
        STS64(sb + SM_VHI(st) + off, pku64(h0, h1));
        STS64(sb + SM_VLO(st) + off, pku64(l0, l1));
    }
}

__global__ void __launch_bounds__(NT, 2) attn_hmma(
    const float* __restrict__ q_g,
    const float* __restrict__ k_g,
    const float* __restrict__ v_g,
    float* __restrict__ out_g)
{
    extern __shared__ char smem[];
    const uint32_t sb = smem_u32(smem);
    float* lred = reinterpret_cast<float*>(smem + SM_LRED);

    const int tid  = threadIdx.x;
    const int lane = tid & 31;
    const int w    = tid >> 5;
    const int wq   = w & 3;     // 16-q-row group
    const int wk   = w >> 2;    // 32-col half (k for QK, dv for PV)
    const int h  = blockIdx.y;
    const int b  = blockIdx.z;
    const int q0 = blockIdx.x * TQ;
    const int hk = h * KSK;

    // ---- prologue: stage Q (split bf16, SW128) into its OWN region; K/V tile 0 ----
    {
        const float4* qg4 = reinterpret_cast<const float4*>(q_g);
        int row = tid >> 2;
        int qb  = (tid & 3) * 4;
        uint32_t swr = (uint32_t)((row & 7) << 4);
        #pragma unroll
        for (int jj = 0; jj < 4; ++jj) {
            float4 qv = qg4[((size_t)(b * KH + h) * KSQ + q0 + row) * 16 + qb + jj];
            uint32_t h0, l0, h1, l1;
            split2(qv.x, qv.y, h0, l0);
            split2(qv.z, qv.w, h1, l1);
            uint32_t off = (uint32_t)(row * 128) + (((uint32_t)((qb + jj) * 8)) ^ swr);
            STS64(sb + SM_QHI + off, pku64(h0, h1));
            STS64(sb + SM_QLO + off, pku64(l0, l1));
        }
    }
    load_kv(sb, 0, reinterpret_cast<const float4*>(k_g), v_g, hk, 0, tid);
    __syncthreads();

    // ---- per-lane ldmatrix addressing ----
    const int mat = lane >> 3, mr = lane & 7;
    const int arow = wq * 16 + ((mat & 1) << 3) + mr;       // A frag row
    const uint32_t arb = (uint32_t)(arow * 128);
    const uint32_t asw = (uint32_t)((arow & 7) << 4);
    const uint32_t akhi = (uint32_t)((mat >> 1) << 4);      // A k-byte half
    const int bn0 = wk * 32 + ((mat >> 1) << 3) + mr;       // B frag row (= n)
    const uint32_t brb0 = (uint32_t)(bn0 * 128);
    const uint32_t brb1 = brb0 + 16 * 128;
    const uint32_t bsw = (uint32_t)((bn0 & 7) << 4);
    const uint32_t bkhi = (uint32_t)((mat & 1) << 4);       // B k-byte half

    float o[4][4];
    #pragma unroll
    for (int nt = 0; nt < 4; ++nt)
        #pragma unroll
        for (int i = 0; i < 4; ++i) o[nt][i] = 0.f;
    float lp0 = 0.f, lp1 = 0.f;

    const int rowq0 = wq * 16 + (lane >> 2);          // score/output row (and +8)
    const int cp    = (lane & 3) * 2;                 // col-pair within 8
    const uint32_t hb0 = ((uint32_t)b << 26) |
                         ((uint32_t)(h * KSQ + q0 + rowq0) << 11);
    const uint32_t hb1 = hb0 + (8u << 11);
    const uint32_t psw  = (uint32_t)((rowq0 & 7) << 4);   // same for rowq0+8
    const uint32_t prb0 = (uint32_t)(rowq0 * 128);
    const uint32_t prb1 = prb0 + 8 * 128;
    const uint32_t pcb  = (uint32_t)(wk * 64 + cp * 2);   // P col byte base

    const float4* kg4 = reinterpret_cast<const float4*>(k_g);

    for (int kt = 0; kt < NTILES; ++kt) {
        const int cur = kt & 1;

        // ---- [A] S = Q K^T (split: hh + hl + lh); Q frags from smem ----
        float s[4][4];
        #pragma unroll
        for (int nt = 0; nt < 4; ++nt)
            #pragma unroll
            for (int i = 0; i < 4; ++i) s[nt][i] = 0.f;

        #pragma unroll
        for (int ch = 0; ch < 4; ++ch) {
            uint32_t qkb = ((uint32_t)(ch * 32) + akhi) ^ asw;
            uint32_t qh[4], ql[4];
            LDMX4(qh, sb + SM_QHI + arb + qkb);
            LDMX4(ql, sb + SM_QLO + arb + qkb);
            uint32_t kb = ((uint32_t)(ch * 32) + bkhi) ^ bsw;
            uint32_t bh0[4], bl0[4], bh1[4], bl1[4];
            LDMX4(bh0, sb + SM_KHI(cur) + brb0 + kb);
            LDMX4(bl0, sb + SM_KLO(cur) + brb0 + kb);
            LDMX4(bh1, sb + SM_KHI(cur) + brb1 + kb);
            LDMX4(bl1, sb + SM_KLO(cur) + brb1 + kb);
            MMA16816(s[0], qh, bh0[0], bh0[1]);
            MMA16816(s[0], qh, bl0[0], bl0[1]);
            MMA16816(s[0], ql, bh0[0], bh0[1]);
            MMA16816(s[1], qh, bh0[2], bh0[3]);
            MMA16816(s[1], qh, bl0[2], bl0[3]);
            MMA16816(s[1], ql, bh0[2], bh0[3]);
            MMA16816(s[2], qh, bh1[0], bh1[1]);
            MMA16816(s[2], qh, bl1[0], bl1[1]);
            MMA16816(s[2], ql, bh1[0], bh1[1]);
            MMA16816(s[3], qh, bh1[2], bh1[3]);
            MMA16816(s[3], qh, bl1[2], bl1[3]);
            MMA16816(s[3], ql, bh1[2], bh1[3]);
        }

        // ---- [B] exp + dropout mask (4-way interleaved threefry) + pack P ----
        uint32_t ph01[4], pl01[4], ph23[4], pl23[4];
        const uint32_t kb0 = hb0 | (uint32_t)(kt * 64 + wk * 32);
        const uint32_t kb1 = hb1 | (uint32_t)(kt * 64 + wk * 32);
        #pragma unroll
        for (int nt = 0; nt < 4; ++nt) {
            uint32_t colw = (uint32_t)(nt * 8 + cp);
            float e0 = ex2f(fmaf(s[nt][0], L2E, NEGC));
            float e1 = ex2f(fmaf(s[nt][1], L2E, NEGC));
            float e2 = ex2f(fmaf(s[nt][2], L2E, NEGC));
            float e3 = ex2f(fmaf(s[nt][3], L2E, NEGC));
            lp0 += e0 + e1;
            lp1 += e2 + e3;
            uint32_t bb0, bb1, bb2, bb3;
            tf32_hash4(kb0 + colw, kb0 + colw + 1u,
                       kb1 + colw, kb1 + colw + 1u,
                       bb0, bb1, bb2, bb3);
            float p0 = (bb0 < KEEP_THRESH) ? e0 : 0.f;
            float p1 = (bb1 < KEEP_THRESH) ? e1 : 0.f;
            float p2 = (bb2 < KEEP_THRESH) ? e2 : 0.f;
            float p3 = (bb3 < KEEP_THRESH) ? e3 : 0.f;
            split2(p0, p1, ph01[nt], pl01[nt]);
            split2(p2, p3, ph23[nt], pl23[nt]);
        }

        __syncthreads();   // [C] prev PV done reading P; next KV stage free

        // ---- [D] store P; prefetch next K/V tile ----
        #pragma unroll
        for (int nt = 0; nt < 4; ++nt) {
            uint32_t co = (pcb + (uint32_t)(nt * 16)) ^ psw;
            STS32(sb + SM_PHI + prb0 + co, ph01[nt]);
            STS32(sb + SM_PLO + prb0 + co, pl01[nt]);
            STS32(sb + SM_PHI + prb1 + co, ph23[nt]);
            STS32(sb + SM_PLO + prb1 + co, pl23[nt]);
        }
        if (kt + 1 < NTILES)
            load_kv(sb, cur ^ 1, kg4, v_g, hk, (kt + 1) * TK, tid);

        __syncthreads();   // [E] P and KV visible

        // ---- [F] O += P V   (split: hh + hl + lh) ----
        #pragma unroll
        for (int ch = 0; ch < 4; ++ch) {
            uint32_t akb = ((uint32_t)(ch * 32) + akhi) ^ asw;
            uint32_t ah[4], al[4];
            LDMX4(ah, sb + SM_PHI + arb + akb);
            LDMX4(al, sb + SM_PLO + arb + akb);
            uint32_t kb = ((uint32_t)(ch * 32) + bkhi) ^ bsw;
            uint32_t bh0[4], bl0[4], bh1[4], bl1[4];
            LDMX4(bh0, sb + SM_VHI(cur) + brb0 + kb);
            LDMX4(bl0, sb + SM_VLO(cur) + brb0 + kb);
            LDMX4(bh1, sb + SM_VHI(cur) + brb1 + kb);
            LDMX4(bl1, sb + SM_VLO(cur) + brb1 + kb);
            MMA16816(o[0], ah, bh0[0], bh0[1]);
            MMA16816(o[0], ah, bl0[0], bl0[1]);
            MMA16816(o[0], al, bh0[0], bh0[1]);
            MMA16816(o[1], ah, bh0[2], bh0[3]);
            MMA16816(o[1], ah, bl0[2], bl0[3]);
            MMA16816(o[1], al, bh0[2], bh0[3]);
            MMA16816(o[2], ah, bh1[0], bh1[1]);
            MMA16816(o[2], ah, bl1[0], bl1[1]);
            MMA16816(o[2], al, bh1[0], bh1[1]);
            MMA16816(o[3], ah, bh1[2], bh1[3]);
            MMA16816(o[3], ah, bl1[2], bl1[3]);
            MMA16816(o[3], al, bh1[2], bh1[3]);
        }
    }

    // ---- l reduction: butterfly over the 4 col-lanes, combine 2 warp-halves ----
    lp0 += __shfl_xor_sync(0xffffffffu, lp0, 1);
    lp0 += __shfl_xor_sync(0xffffffffu, lp0, 2);
    lp1 += __shfl_xor_sync(0xffffffffu, lp1, 1);
    lp1 += __shfl_xor_sync(0xffffffffu, lp1, 2);
    if ((lane & 3) == 0) {
        lred[wk * 64 + rowq0]     = lp0;
        lred[wk * 64 + rowq0 + 8] = lp1;
    }
    __syncthreads();
    const float fin = 0.5f / 0.9f;
    const float sc0 = fin / (lred[rowq0]     + lred[64 + rowq0]);
    const float sc1 = fin / (lred[rowq0 + 8] + lred[64 + rowq0 + 8]);

    // ---- epilogue ----
    float2* out2 = reinterpret_cast<float2*>(out_g);
    const size_t ob0 = ((size_t)(b * KH + h) * KSQ + q0 + rowq0) * 32;
    #pragma unroll
    for (int nt = 0; nt < 4; ++nt) {
        int c2 = (wk * 32 + nt * 8 + cp) >> 1;
        out2[ob0 + c2] = make_float2(o[nt][0] * sc0, o[nt][1] * sc0);
        out2[ob0 + 8 * 32 + c2] = make_float2(o[nt][2] * sc1, o[nt][3] * sc1);
    }
}

extern "C" void kernel_launch(void* const* d_in, const int* in_sizes, int n_in,
                              void* d_out, int out_size) {
    (void)in_sizes; (void)n_in; (void)out_size;
    const float* q = (const float*)d_in[0];
    const float* k = (const float*)d_in[1];
    const float* v = (const float*)d_in[2];
    float* out = (float*)d_out;

    cudaFuncSetAttribute(attn_hmma,
                         cudaFuncAttributeMaxDynamicSharedMemorySize, SMEM_BYTES);
    dim3 grid(KSQ / TQ, KH, KB);   // (32, 16, 2) = 1024 CTAs
    attn_hmma<<<grid, NT, SMEM_BYTES>>>(q, k, v, out);
}